// round 12
// baseline (speedup 1.0000x reference)
#include <cuda_runtime.h>
#include <cuda_fp16.h>
#include <math_constants.h>

#define N_NODES 50000
#define N_EDGES 800000
#define HEADS   3
#define HF      64            // H_FEATS
#define HFO     (HEADS*HF)    // 192
#define NH2     (HFO/2)       // 96 half2 per node row (= 24 float4)
#define NF4     24            // float4 per node row
#define NCLS    2
#define HFO3    (HEADS*NCLS)  // 6
#define NEG     0.2f
#define WPB     8             // warps per block for per-dst kernels
#define SCAN_B  1024
#define SCAN_NB ((N_NODES + SCAN_B - 1) / SCAN_B)   // 49

typedef unsigned long long ull;

// ---------------- scratch (device globals; no allocation allowed) ----------
__device__ __align__(16) __half2 g_feath[N_NODES * NH2];  // fp16 feat [N][96] half2
__device__ __align__(16) float   g_el  [N_NODES * 4];     // el per node (padded)
__device__ __align__(16) float   g_er  [N_NODES * 4];     // er per node (padded)
__device__ __align__(16) float   g_h   [N_NODES * HF];    // inter-layer node feats
__device__ float g_feat3[N_NODES * HFO3];                 // layer-3 feat (fp32)
__device__ int   g_csrs [N_EDGES];                        // src node per CSR slot
__device__ int   g_rowp [N_NODES + 1];                    // CSR row pointers (by dst)
__device__ int   g_cnt  [N_NODES];                        // in-degree histogram
__device__ int   g_wpos [N_NODES];                        // scatter cursors
__device__ int   g_bsum [64];                             // scan block sums

// ---------------- helpers ---------------------------------------------------
__device__ __forceinline__ float lrelu(float v) { return v > 0.f ? v : NEG * v; }
__device__ __forceinline__ float wred_sum(float v) {
#pragma unroll
    for (int o = 16; o; o >>= 1) v += __shfl_xor_sync(~0u, v, o);
    return v;
}
__device__ __forceinline__ ull pack2(float lo, float hi) {
    ull r; asm("mov.b64 %0, {%1, %2};" : "=l"(r) : "f"(lo), "f"(hi)); return r;
}
__device__ __forceinline__ void fma2(ull& d, ull a, ull b) {
    asm("fma.rn.f32x2 %0, %1, %2, %0;" : "+l"(d) : "l"(a), "l"(b));
}
__device__ __forceinline__ float2 unpack2(ull v) {
    float2 f; asm("mov.b64 {%0, %1}, %2;" : "=f"(f.x), "=f"(f.y) : "l"(v)); return f;
}

// ================= CSR build ================================================
__global__ void hist_dst(const int4* __restrict__ dst4) {
    int t = blockIdx.x * blockDim.x + threadIdx.x;
    if (t >= N_EDGES / 4) return;
    int4 d = __ldg(&dst4[t]);
    atomicAdd(&g_cnt[d.x], 1);
    atomicAdd(&g_cnt[d.y], 1);
    atomicAdd(&g_cnt[d.z], 1);
    atomicAdd(&g_cnt[d.w], 1);
}
// ---- 3-phase parallel exclusive scan over g_cnt ----
__global__ void scan_local() {
    __shared__ int wsum[32];
    const int idx  = blockIdx.x * SCAN_B + threadIdx.x;
    const int lane = threadIdx.x & 31, w = threadIdx.x >> 5;
    int v = (idx < N_NODES) ? g_cnt[idx] : 0;
    int x = v;
#pragma unroll
    for (int o = 1; o < 32; o <<= 1) {
        int y = __shfl_up_sync(~0u, x, o);
        if (lane >= o) x += y;
    }
    if (lane == 31) wsum[w] = x;
    __syncthreads();
    if (w == 0) {
        int y = wsum[lane];
#pragma unroll
        for (int o = 1; o < 32; o <<= 1) {
            int z = __shfl_up_sync(~0u, y, o);
            if (lane >= o) y += z;
        }
        wsum[lane] = y;
    }
    __syncthreads();
    int excl = x - v + (w > 0 ? wsum[w - 1] : 0);
    if (idx < N_NODES) g_rowp[idx] = excl;
    if (threadIdx.x == SCAN_B - 1) g_bsum[blockIdx.x] = excl + v;
}
__global__ void scan_bsum() {   // 1 block, 64 threads
    __shared__ int ws[2];
    const int t = threadIdx.x, lane = t & 31, w = t >> 5;
    int v = (t < SCAN_NB) ? g_bsum[t] : 0;
    int x = v;
#pragma unroll
    for (int o = 1; o < 32; o <<= 1) {
        int y = __shfl_up_sync(~0u, x, o);
        if (lane >= o) x += y;
    }
    if (lane == 31) ws[w] = x;
    __syncthreads();
    int excl = x - v + (w == 1 ? ws[0] : 0);
    g_bsum[t] = excl;
}
__global__ void scan_add() {
    const int idx = blockIdx.x * SCAN_B + threadIdx.x;
    if (idx < N_NODES) {
        int r = g_rowp[idx] + g_bsum[blockIdx.x];
        g_rowp[idx] = r;
        g_wpos[idx] = r;
    }
    if (idx == 0) g_rowp[N_NODES] = N_EDGES;
}
__global__ void scatter_edges(const int4* __restrict__ src4, const int4* __restrict__ dst4) {
    int t = blockIdx.x * blockDim.x + threadIdx.x;
    if (t >= N_EDGES / 4) return;
    int4 s = __ldg(&src4[t]);
    int4 d = __ldg(&dst4[t]);
    g_csrs[atomicAdd(&g_wpos[d.x], 1)] = s.x;
    g_csrs[atomicAdd(&g_wpos[d.y], 1)] = s.y;
    g_csrs[atomicAdd(&g_wpos[d.z], 1)] = s.z;
    g_csrs[atomicAdd(&g_wpos[d.w], 1)] = s.w;
}

// ================= fused GEMM + attn dots (HFo = 192), packed f32x2 =========
template <int FIN>
__global__ void gemm_attn(const float* __restrict__ x,
                          const float* __restrict__ W,
                          const float* __restrict__ al,
                          const float* __restrict__ ar,
                          __half2* __restrict__ feath) {
    __shared__ float xs[FIN][34];
    const int tid = threadIdx.x;
    const int cg  = tid % 48;
    const int ng  = tid / 48;
    const int n0  = blockIdx.x * 32;
    const int head = cg / 16;
    const int c64  = (cg % 16) * 4;

    for (int i = tid; i < 32 * FIN; i += 192) {
        int node = i / FIN, k = i % FIN;
        int gn = n0 + node;
        xs[k][node] = (gn < N_NODES) ? x[gn * FIN + k] : 0.f;
    }
    __syncthreads();

    ull acc2[4][4];
#pragma unroll
    for (int p = 0; p < 4; p++)
#pragma unroll
        for (int j = 0; j < 4; j++) acc2[p][j] = 0ull;

    for (int k = 0; k < FIN; k++) {
        float4 w = __ldg(reinterpret_cast<const float4*>(W + k * HFO + cg * 4));
        ull wd0 = pack2(w.x, w.x), wd1 = pack2(w.y, w.y);
        ull wd2 = pack2(w.z, w.z), wd3 = pack2(w.w, w.w);
        const float* row = &xs[k][ng * 8];
#pragma unroll
        for (int p = 0; p < 4; p++) {
            ull xp = *reinterpret_cast<const ull*>(row + 2 * p);
            fma2(acc2[p][0], xp, wd0);
            fma2(acc2[p][1], xp, wd1);
            fma2(acc2[p][2], xp, wd2);
            fma2(acc2[p][3], xp, wd3);
        }
    }

    float a[8][4];
#pragma unroll
    for (int p = 0; p < 4; p++)
#pragma unroll
        for (int j = 0; j < 4; j++) {
            float2 f = unpack2(acc2[p][j]);
            a[2 * p][j]     = f.x;
            a[2 * p + 1][j] = f.y;
        }

#pragma unroll
    for (int i = 0; i < 8; i++) {
        int node = n0 + ng * 8 + i;
        if (node < N_NODES) {
            __half2 h0 = __floats2half2_rn(a[i][0], a[i][1]);
            __half2 h1 = __floats2half2_rn(a[i][2], a[i][3]);
            uint2 pk = make_uint2(*reinterpret_cast<unsigned*>(&h0),
                                  *reinterpret_cast<unsigned*>(&h1));
            *reinterpret_cast<uint2*>(feath + node * NH2 + cg * 2) = pk;
        }
    }

    float a0 = __ldg(&al[head * HF + c64 + 0]), a1 = __ldg(&al[head * HF + c64 + 1]);
    float a2 = __ldg(&al[head * HF + c64 + 2]), a3 = __ldg(&al[head * HF + c64 + 3]);
    float r0 = __ldg(&ar[head * HF + c64 + 0]), r1 = __ldg(&ar[head * HF + c64 + 1]);
    float r2 = __ldg(&ar[head * HF + c64 + 2]), r3 = __ldg(&ar[head * HF + c64 + 3]);
#pragma unroll
    for (int i = 0; i < 8; i++) {
        float sl = a[i][0]*a0 + a[i][1]*a1 + a[i][2]*a2 + a[i][3]*a3;
        float sr = a[i][0]*r0 + a[i][1]*r1 + a[i][2]*r2 + a[i][3]*r3;
#pragma unroll
        for (int o = 8; o; o >>= 1) {
            sl += __shfl_down_sync(~0u, sl, o, 16);
            sr += __shfl_down_sync(~0u, sr, o, 16);
        }
        if ((tid & 15) == 0) {
            int node = n0 + ng * 8 + i;
            if (node < N_NODES) {
                g_el[node * 4 + head] = sl;
                g_er[node * 4 + head] = sr;
            }
        }
    }
}

// ================= fused layer-3 GEMM + attn dots (HFo = 6) =================
__global__ void gemm3_attn(const float* __restrict__ x,
                           const float* __restrict__ W,
                           const float* __restrict__ al,
                           const float* __restrict__ ar) {
    int n = blockIdx.x * blockDim.x + threadIdx.x;
    if (n >= N_NODES) return;
    float acc[HFO3];
#pragma unroll
    for (int c = 0; c < HFO3; c++) acc[c] = 0.f;
    const float4* xr = reinterpret_cast<const float4*>(x + n * HF);
    for (int k4 = 0; k4 < HF / 4; k4++) {
        float4 xv = __ldg(xr + k4);
#pragma unroll
        for (int c = 0; c < HFO3; c++) {
            acc[c] += xv.x * __ldg(&W[(k4*4+0) * HFO3 + c]);
            acc[c] += xv.y * __ldg(&W[(k4*4+1) * HFO3 + c]);
            acc[c] += xv.z * __ldg(&W[(k4*4+2) * HFO3 + c]);
            acc[c] += xv.w * __ldg(&W[(k4*4+3) * HFO3 + c]);
        }
    }
#pragma unroll
    for (int c = 0; c < HFO3; c++) g_feat3[n * HFO3 + c] = acc[c];
#pragma unroll
    for (int h = 0; h < HEADS; h++) {
        g_el[n * 4 + h] = acc[h*NCLS+0] * __ldg(&al[h*NCLS+0]) + acc[h*NCLS+1] * __ldg(&al[h*NCLS+1]);
        g_er[n * 4 + h] = acc[h*NCLS+0] * __ldg(&ar[h*NCLS+0]) + acc[h*NCLS+1] * __ldg(&ar[h*NCLS+1]);
    }
}

// ================= prime out with head-summed bias ==========================
__global__ void prime_bias(float* __restrict__ out, const float* __restrict__ bias) {
    int idx = blockIdx.x * blockDim.x + threadIdx.x;   // over N*HF
    if (idx >= N_NODES * HF) return;
    int c = idx & (HF - 1);
    out[idx] = __ldg(&bias[c]) + __ldg(&bias[HF + c]) + __ldg(&bias[2 * HF + c]);
}

// ================= fused softmax + aggregation, one warp per (dst, head) ====
// 8 lanes per edge (128B row slice), 4 edges per warp step, all lanes active.
// Output accumulated into bias-primed `out` via red.global (head-sum for free).
__global__ void agg_bigh(const float4* __restrict__ ff4,   // g_feath as float4[N][24]
                         float* __restrict__ out) {
    __shared__ int   s_off[WPB][32];
    __shared__ float s_w[WPB][32];
    const int lane = threadIdx.x & 31;
    const int wrp  = threadIdx.x >> 5;
    const int unit = blockIdx.x * WPB + wrp;     // (d, h) unit; grid covers exactly
    const int d = unit / 3, h = unit - 3 * d;
    const int beg = g_rowp[d], end = g_rowp[d + 1];
    const float erh = g_er[4 * d + h];
    const int eslot = lane >> 3;                 // which of 4 concurrent edges
    const int q     = lane & 7;                  // float4 slot within 128B row

    float acc[8];
#pragma unroll
    for (int k = 0; k < 8; k++) acc[k] = 0.f;
    float wsum = 0.f;

    for (int base = beg; base < end; base += 32) {
        int i = base + lane;
        float wl = 0.f; int off = 0;
        if (i < end) {
            int s = __ldg(&g_csrs[i]);
            wl = __expf(lrelu(__ldg(&g_el[4 * s + h]) + erh));
            off = s * NF4 + h * 8;
        }
        wsum += wl;
        s_off[wrp][lane] = off;
        s_w[wrp][lane]   = wl;
        __syncwarp();
        const int cnt = min(32, end - base);
        for (int j = 0; j < cnt; j += 4) {
            const int e = j + eslot;
            if (e < cnt) {
                const float w = s_w[wrp][e];
                float4 v = __ldg(ff4 + s_off[wrp][e] + q);
                const __half2* hv = reinterpret_cast<const __half2*>(&v);
                float2 f0 = __half22float2(hv[0]);
                float2 f1 = __half22float2(hv[1]);
                float2 f2 = __half22float2(hv[2]);
                float2 f3 = __half22float2(hv[3]);
                acc[0] += w * f0.x;  acc[1] += w * f0.y;
                acc[2] += w * f1.x;  acc[3] += w * f1.y;
                acc[4] += w * f2.x;  acc[5] += w * f2.y;
                acc[6] += w * f3.x;  acc[7] += w * f3.y;
            }
        }
        __syncwarp();
    }
    wsum = wred_sum(wsum);
    const float inv = wsum > 0.f ? 1.f / wsum : 0.f;

    // reduce over the 4 edge-slots (lanes l, l^8, l^16, l^24)
#pragma unroll
    for (int k = 0; k < 8; k++) {
        acc[k] += __shfl_xor_sync(~0u, acc[k], 8);
        acc[k] += __shfl_xor_sync(~0u, acc[k], 16);
    }
    if (lane < 8) {                              // lane == q, eslot 0
#pragma unroll
        for (int k = 0; k < 8; k++) acc[k] *= inv;
        float* rp = out + d * HF + lane * 8;     // head-h contribution, cols 8q..8q+7
        asm volatile("red.global.add.v4.f32 [%0], {%1,%2,%3,%4};"
                     :: "l"(rp), "f"(acc[0]), "f"(acc[1]), "f"(acc[2]), "f"(acc[3])
                     : "memory");
        asm volatile("red.global.add.v4.f32 [%0], {%1,%2,%3,%4};"
                     :: "l"(rp + 4), "f"(acc[4]), "f"(acc[5]), "f"(acc[6]), "f"(acc[7])
                     : "memory");
    }
}

// ================= fused softmax + aggregation, Fo = 2 (layer 3) ============
__global__ void agg_small(const float* __restrict__ feat,
                          const float* __restrict__ bias,
                          float* __restrict__ out) {
    const int lane = threadIdx.x & 31;
    const int d = blockIdx.x * WPB + (threadIdx.x >> 5);
    if (d >= N_NODES) return;
    const int beg = g_rowp[d], end = g_rowp[d + 1];
    const float4 er = *reinterpret_cast<const float4*>(g_er + 4 * d);

    float s0 = 0.f, s1 = 0.f, s2 = 0.f;
    float c00 = 0.f, c01 = 0.f, c10 = 0.f, c11 = 0.f, c20 = 0.f, c21 = 0.f;
    for (int i = beg + lane; i < end; i += 32) {
        int s = __ldg(&g_csrs[i]);
        float4 e = *reinterpret_cast<const float4*>(g_el + 4 * s);
        float w0 = __expf(lrelu(e.x + er.x));
        float w1 = __expf(lrelu(e.y + er.y));
        float w2 = __expf(lrelu(e.z + er.z));
        s0 += w0; s1 += w1; s2 += w2;
        const float* fp = feat + s * HFO3;
        c00 += w0 * __ldg(fp + 0); c01 += w0 * __ldg(fp + 1);
        c10 += w1 * __ldg(fp + 2); c11 += w1 * __ldg(fp + 3);
        c20 += w2 * __ldg(fp + 4); c21 += w2 * __ldg(fp + 5);
    }
    s0 = wred_sum(s0); s1 = wred_sum(s1); s2 = wred_sum(s2);
    c00 = wred_sum(c00); c01 = wred_sum(c01);
    c10 = wred_sum(c10); c11 = wred_sum(c11);
    c20 = wred_sum(c20); c21 = wred_sum(c21);
    if (lane == 0) {
        const float i0 = s0 > 0.f ? 1.f / s0 : 0.f;
        const float i1 = s1 > 0.f ? 1.f / s1 : 0.f;
        const float i2 = s2 > 0.f ? 1.f / s2 : 0.f;
        float b0 = __ldg(&bias[0]) + __ldg(&bias[2]) + __ldg(&bias[4]);
        float b1 = __ldg(&bias[1]) + __ldg(&bias[3]) + __ldg(&bias[5]);
        out[d * NCLS + 0] = c00 * i0 + c10 * i1 + c20 * i2 + b0;
        out[d * NCLS + 1] = c01 * i0 + c11 * i1 + c21 * i2 + b1;
    }
}

// ================= host driver ==============================================
static inline int cdiv(int a, int b) { return (a + b - 1) / b; }

extern "C" void kernel_launch(void* const* d_in, const int* in_sizes, int n_in,
                              void* d_out, int out_size) {
    const float* feats = (const float*)d_in[0];
    const int*   src   = (const int*)  d_in[1];
    const int*   dst   = (const int*)  d_in[2];
    const float* W1 = (const float*)d_in[3],  *al1 = (const float*)d_in[4];
    const float* ar1= (const float*)d_in[5],  *b1  = (const float*)d_in[6];
    const float* W2 = (const float*)d_in[7],  *al2 = (const float*)d_in[8];
    const float* ar2= (const float*)d_in[9],  *b2  = (const float*)d_in[10];
    const float* W3 = (const float*)d_in[11], *al3 = (const float*)d_in[12];
    const float* ar3= (const float*)d_in[13], *b3  = (const float*)d_in[14];
    float* out = (float*)d_out;

    __half2* feath;
    float *h, *feat3;
    int* cnt;
    cudaGetSymbolAddress((void**)&feath, g_feath);
    cudaGetSymbolAddress((void**)&h,     g_h);
    cudaGetSymbolAddress((void**)&feat3, g_feat3);
    cudaGetSymbolAddress((void**)&cnt,   g_cnt);
    const float4* ff4 = reinterpret_cast<const float4*>(feath);

    const int gE4   = cdiv(N_EDGES / 4, 256);
    const int gTile = cdiv(N_NODES, 32);
    const int gDst  = cdiv(N_NODES, WPB);
    const int gUnit = cdiv(N_NODES * HEADS, WPB);     // 18750 exactly
    const int gPrime= cdiv(N_NODES * HF, 256);

    // -------- CSR build (graph shared by all 3 layers) --------
    cudaMemsetAsync(cnt, 0, N_NODES * sizeof(int));
    hist_dst<<<gE4, 256>>>((const int4*)dst);
    scan_local<<<SCAN_NB, SCAN_B>>>();
    scan_bsum<<<1, 64>>>();
    scan_add<<<SCAN_NB, SCAN_B>>>();
    scatter_edges<<<gE4, 256>>>((const int4*)src, (const int4*)dst);

    // -------- layer 1 (Fin=9, Fo=64) --------
    gemm_attn<9><<<gTile, 192>>>(feats, W1, al1, ar1, feath);
    prime_bias<<<gPrime, 256>>>(h, b1);
    agg_bigh<<<gUnit, 32 * WPB>>>(ff4, h);

    // -------- layer 2 (Fin=64, Fo=64) --------
    gemm_attn<64><<<gTile, 192>>>(h, W2, al2, ar2, feath);
    prime_bias<<<gPrime, 256>>>(h, b2);
    agg_bigh<<<gUnit, 32 * WPB>>>(ff4, h);

    // -------- layer 3 (Fin=64, Fo=2) --------
    gemm3_attn<<<cdiv(N_NODES, 128), 128>>>(h, W3, al3, ar3);
    agg_small<<<gDst, 32 * WPB>>>(feat3, b3, out);
}

// round 13
// speedup vs baseline: 1.2724x; 1.2724x over previous
#include <cuda_runtime.h>
#include <cuda_fp16.h>
#include <math_constants.h>

#define N_NODES 50000
#define N_EDGES 800000
#define HEADS   3
#define HF      64            // H_FEATS
#define HFO     (HEADS*HF)    // 192
#define NH2     (HFO/2)       // 96 half2 per node row (= 24 float4)
#define NCLS    2
#define HFO3    (HEADS*NCLS)  // 6
#define NEG     0.2f
#define WPB     8             // warps per block for per-dst kernels
#define SCAN_B  1024
#define SCAN_NB ((N_NODES + SCAN_B - 1) / SCAN_B)   // 49
#define GT1     ((N_NODES + 31) / 32)               // 1563 gemm tiles
#define SCB     ((N_EDGES / 4 + 191) / 192)         // 1042 scatter blocks

typedef unsigned long long ull;

// ---------------- scratch (device globals; no allocation allowed) ----------
__device__ __align__(16) __half2 g_feath[N_NODES * NH2];  // fp16 feat [N][96] half2
__device__ __align__(16) float   g_el  [N_NODES * 4];     // el per node (padded)
__device__ __align__(16) float   g_er  [N_NODES * 4];     // er per node (padded)
__device__ float g_h    [N_NODES * HF];                   // inter-layer node feats
__device__ float g_feat3[N_NODES * HFO3];                 // layer-3 feat (fp32)
__device__ int   g_csrs [N_EDGES];                        // src node per CSR slot
__device__ int   g_rowp [N_NODES + 1];                    // CSR row pointers (by dst)
__device__ int   g_cnt  [N_NODES];                        // in-degree histogram
__device__ int   g_wpos [N_NODES];                        // scatter cursors
__device__ int   g_bsum [64];                             // scan block sums

// ---------------- helpers ---------------------------------------------------
__device__ __forceinline__ float lrelu(float v) { return v > 0.f ? v : NEG * v; }
__device__ __forceinline__ float wred_sum(float v) {
#pragma unroll
    for (int o = 16; o; o >>= 1) v += __shfl_xor_sync(~0u, v, o);
    return v;
}
__device__ __forceinline__ ull pack2(float lo, float hi) {
    ull r; asm("mov.b64 %0, {%1, %2};" : "=l"(r) : "f"(lo), "f"(hi)); return r;
}
__device__ __forceinline__ void fma2(ull& d, ull a, ull b) {
    asm("fma.rn.f32x2 %0, %1, %2, %0;" : "+l"(d) : "l"(a), "l"(b));
}
__device__ __forceinline__ float2 unpack2(ull v) {
    float2 f; asm("mov.b64 {%0, %1}, %2;" : "=f"(f.x), "=f"(f.y) : "l"(v)); return f;
}

// ================= CSR build ================================================
__global__ void hist_dst(const int4* __restrict__ dst4) {
    int t = blockIdx.x * blockDim.x + threadIdx.x;
    if (t >= N_EDGES / 4) return;
    int4 d = __ldg(&dst4[t]);
    atomicAdd(&g_cnt[d.x], 1);
    atomicAdd(&g_cnt[d.y], 1);
    atomicAdd(&g_cnt[d.z], 1);
    atomicAdd(&g_cnt[d.w], 1);
}
// phase 1: per-block local exclusive scan; publish block sums
__global__ void scan_local() {
    __shared__ int wsum[32];
    const int idx  = blockIdx.x * SCAN_B + threadIdx.x;
    const int lane = threadIdx.x & 31, w = threadIdx.x >> 5;
    int v = (idx < N_NODES) ? g_cnt[idx] : 0;
    int x = v;
#pragma unroll
    for (int o = 1; o < 32; o <<= 1) {
        int y = __shfl_up_sync(~0u, x, o);
        if (lane >= o) x += y;
    }
    if (lane == 31) wsum[w] = x;
    __syncthreads();
    if (w == 0) {
        int y = wsum[lane];
#pragma unroll
        for (int o = 1; o < 32; o <<= 1) {
            int z = __shfl_up_sync(~0u, y, o);
            if (lane >= o) y += z;
        }
        wsum[lane] = y;
    }
    __syncthreads();
    int excl = x - v + (w > 0 ? wsum[w - 1] : 0);
    if (idx < N_NODES) g_rowp[idx] = excl;
    if (threadIdx.x == SCAN_B - 1) g_bsum[blockIdx.x] = excl + v;
}
// phase 2 (fused): each block redundantly reduces bsum[0..bid) and adds it
__global__ void scan_add2() {
    __shared__ int psum[2];
    const int t = threadIdx.x, lane = t & 31, w = t >> 5;
    if (t < 64) {
        int j = t;
        int v = (j < SCAN_NB && j < (int)blockIdx.x) ? g_bsum[j] : 0;
        v = wred_sum(v);
        if (lane == 0) psum[w] = v;
    }
    __syncthreads();
    const int pref = psum[0] + psum[1];
    const int idx = blockIdx.x * SCAN_B + t;
    if (idx < N_NODES) {
        int r = g_rowp[idx] + pref;
        g_rowp[idx] = r;
        g_wpos[idx] = r;
    }
    if (blockIdx.x == 0 && t == 0) g_rowp[N_NODES] = N_EDGES;
}

// ================= gemm body (shared by fused + standalone kernels) =========
template <int FIN>
__device__ __forceinline__ void gemm_attn_body(
        const float* __restrict__ x, const float* __restrict__ W,
        const float* __restrict__ al, const float* __restrict__ ar,
        __half2* __restrict__ feath, int tile) {
    __shared__ float xs[FIN][34];
    const int tid = threadIdx.x;
    const int cg  = tid % 48;
    const int ng  = tid / 48;
    const int n0  = tile * 32;
    const int head = cg / 16;
    const int c64  = (cg % 16) * 4;

    for (int i = tid; i < 32 * FIN; i += 192) {
        int node = i / FIN, k = i % FIN;
        int gn = n0 + node;
        xs[k][node] = (gn < N_NODES) ? x[gn * FIN + k] : 0.f;
    }
    __syncthreads();

    ull acc2[4][4];
#pragma unroll
    for (int p = 0; p < 4; p++)
#pragma unroll
        for (int j = 0; j < 4; j++) acc2[p][j] = 0ull;

    for (int k = 0; k < FIN; k++) {
        float4 w = __ldg(reinterpret_cast<const float4*>(W + k * HFO + cg * 4));
        ull wd0 = pack2(w.x, w.x), wd1 = pack2(w.y, w.y);
        ull wd2 = pack2(w.z, w.z), wd3 = pack2(w.w, w.w);
        const float* row = &xs[k][ng * 8];
#pragma unroll
        for (int p = 0; p < 4; p++) {
            ull xp = *reinterpret_cast<const ull*>(row + 2 * p);
            fma2(acc2[p][0], xp, wd0);
            fma2(acc2[p][1], xp, wd1);
            fma2(acc2[p][2], xp, wd2);
            fma2(acc2[p][3], xp, wd3);
        }
    }

    float a[8][4];
#pragma unroll
    for (int p = 0; p < 4; p++)
#pragma unroll
        for (int j = 0; j < 4; j++) {
            float2 f = unpack2(acc2[p][j]);
            a[2 * p][j]     = f.x;
            a[2 * p + 1][j] = f.y;
        }

#pragma unroll
    for (int i = 0; i < 8; i++) {
        int node = n0 + ng * 8 + i;
        if (node < N_NODES) {
            __half2 h0 = __floats2half2_rn(a[i][0], a[i][1]);
            __half2 h1 = __floats2half2_rn(a[i][2], a[i][3]);
            uint2 pk = make_uint2(*reinterpret_cast<unsigned*>(&h0),
                                  *reinterpret_cast<unsigned*>(&h1));
            *reinterpret_cast<uint2*>(feath + node * NH2 + cg * 2) = pk;
        }
    }

    float a0 = __ldg(&al[head * HF + c64 + 0]), a1 = __ldg(&al[head * HF + c64 + 1]);
    float a2 = __ldg(&al[head * HF + c64 + 2]), a3 = __ldg(&al[head * HF + c64 + 3]);
    float r0 = __ldg(&ar[head * HF + c64 + 0]), r1 = __ldg(&ar[head * HF + c64 + 1]);
    float r2 = __ldg(&ar[head * HF + c64 + 2]), r3 = __ldg(&ar[head * HF + c64 + 3]);
#pragma unroll
    for (int i = 0; i < 8; i++) {
        float sl = a[i][0]*a0 + a[i][1]*a1 + a[i][2]*a2 + a[i][3]*a3;
        float sr = a[i][0]*r0 + a[i][1]*r1 + a[i][2]*r2 + a[i][3]*r3;
#pragma unroll
        for (int o = 8; o; o >>= 1) {
            sl += __shfl_down_sync(~0u, sl, o, 16);
            sr += __shfl_down_sync(~0u, sr, o, 16);
        }
        if ((tid & 15) == 0) {
            int node = n0 + ng * 8 + i;
            if (node < N_NODES) {
                g_el[node * 4 + head] = sl;
                g_er[node * 4 + head] = sr;
            }
        }
    }
}

// ================= fused: layer-1 GEMM (blocks < GT1) + edge scatter ========
__global__ void gemm1_scatter(const float* __restrict__ x,
                              const float* __restrict__ W,
                              const float* __restrict__ al,
                              const float* __restrict__ ar,
                              __half2* __restrict__ feath,
                              const int4* __restrict__ src4,
                              const int4* __restrict__ dst4) {
    if (blockIdx.x < GT1) {
        gemm_attn_body<9>(x, W, al, ar, feath, blockIdx.x);
    } else {
        int t = (blockIdx.x - GT1) * 192 + threadIdx.x;
        if (t >= N_EDGES / 4) return;
        int4 s = __ldg(&src4[t]);
        int4 d = __ldg(&dst4[t]);
        g_csrs[atomicAdd(&g_wpos[d.x], 1)] = s.x;
        g_csrs[atomicAdd(&g_wpos[d.y], 1)] = s.y;
        g_csrs[atomicAdd(&g_wpos[d.z], 1)] = s.z;
        g_csrs[atomicAdd(&g_wpos[d.w], 1)] = s.w;
    }
}

// ================= standalone layer-2 GEMM ==================================
__global__ void gemm_attn64(const float* __restrict__ x,
                            const float* __restrict__ W,
                            const float* __restrict__ al,
                            const float* __restrict__ ar,
                            __half2* __restrict__ feath) {
    gemm_attn_body<64>(x, W, al, ar, feath, blockIdx.x);
}

// ================= fused layer-3 GEMM + attn dots (HFo = 6) =================
__global__ void gemm3_attn(const float* __restrict__ x,
                           const float* __restrict__ W,
                           const float* __restrict__ al,
                           const float* __restrict__ ar) {
    int n = blockIdx.x * blockDim.x + threadIdx.x;
    if (n >= N_NODES) return;
    float acc[HFO3];
#pragma unroll
    for (int c = 0; c < HFO3; c++) acc[c] = 0.f;
    const float4* xr = reinterpret_cast<const float4*>(x + n * HF);
    for (int k4 = 0; k4 < HF / 4; k4++) {
        float4 xv = __ldg(xr + k4);
#pragma unroll
        for (int c = 0; c < HFO3; c++) {
            acc[c] += xv.x * __ldg(&W[(k4*4+0) * HFO3 + c]);
            acc[c] += xv.y * __ldg(&W[(k4*4+1) * HFO3 + c]);
            acc[c] += xv.z * __ldg(&W[(k4*4+2) * HFO3 + c]);
            acc[c] += xv.w * __ldg(&W[(k4*4+3) * HFO3 + c]);
        }
    }
#pragma unroll
    for (int c = 0; c < HFO3; c++) g_feat3[n * HFO3 + c] = acc[c];
#pragma unroll
    for (int h = 0; h < HEADS; h++) {
        g_el[n * 4 + h] = acc[h*NCLS+0] * __ldg(&al[h*NCLS+0]) + acc[h*NCLS+1] * __ldg(&al[h*NCLS+1]);
        g_er[n * 4 + h] = acc[h*NCLS+0] * __ldg(&ar[h*NCLS+0]) + acc[h*NCLS+1] * __ldg(&ar[h*NCLS+1]);
    }
}

// ================= fused softmax + aggregation, Fo = 64, fp16 gather ========
// one warp per dst (best-measured form, R10/R11).
__global__ void agg_big(const __half2* __restrict__ feath,
                        const float* __restrict__ bias,
                        float* __restrict__ out) {
    __shared__ int   s_off[WPB][32];          // src * NH2 (pre-scaled row offset)
    __shared__ float s_w[WPB][3][32];
    const int lane = threadIdx.x & 31;
    const int wrp  = threadIdx.x >> 5;
    const int d = blockIdx.x * WPB + wrp;
    if (d >= N_NODES) return;
    const int beg = g_rowp[d], end = g_rowp[d + 1];
    const int head = lane >> 3;          // valid for lane < 24

    const float4 er = *reinterpret_cast<const float4*>(g_er + 4 * d);
    float s0 = 0.f, s1 = 0.f, s2 = 0.f;
    float acc[8];
#pragma unroll
    for (int k = 0; k < 8; k++) acc[k] = 0.f;

    for (int base = beg; base < end; base += 32) {
        int i = base + lane;
        int   sl  = 0;
        float w0l = 0.f, w1l = 0.f, w2l = 0.f;
        if (i < end) {
            sl = __ldg(&g_csrs[i]);
            float4 e = *reinterpret_cast<const float4*>(g_el + 4 * sl);
            w0l = __expf(lrelu(e.x + er.x));
            w1l = __expf(lrelu(e.y + er.y));
            w2l = __expf(lrelu(e.z + er.z));
        }
        s0 += w0l; s1 += w1l; s2 += w2l;
        s_off[wrp][lane] = sl * NH2;
        s_w[wrp][0][lane] = w0l;
        s_w[wrp][1][lane] = w1l;
        s_w[wrp][2][lane] = w2l;
        __syncwarp();
        const int cnt = min(32, end - base);
        if (lane < 24) {
            int j = 0;
            for (; j + 2 <= cnt; j += 2) {
                const int   oA = s_off[wrp][j];
                const int   oB = s_off[wrp][j + 1];
                const float wA = s_w[wrp][head][j];
                const float wB = s_w[wrp][head][j + 1];
                float4 vA = __ldg(reinterpret_cast<const float4*>(feath + oA) + lane);
                float4 vB = __ldg(reinterpret_cast<const float4*>(feath + oB) + lane);
                {
                    const __half2* hv = reinterpret_cast<const __half2*>(&vA);
                    float2 f0 = __half22float2(hv[0]), f1 = __half22float2(hv[1]);
                    float2 f2 = __half22float2(hv[2]), f3 = __half22float2(hv[3]);
                    acc[0] += wA * f0.x;  acc[1] += wA * f0.y;
                    acc[2] += wA * f1.x;  acc[3] += wA * f1.y;
                    acc[4] += wA * f2.x;  acc[5] += wA * f2.y;
                    acc[6] += wA * f3.x;  acc[7] += wA * f3.y;
                }
                {
                    const __half2* hv = reinterpret_cast<const __half2*>(&vB);
                    float2 f0 = __half22float2(hv[0]), f1 = __half22float2(hv[1]);
                    float2 f2 = __half22float2(hv[2]), f3 = __half22float2(hv[3]);
                    acc[0] += wB * f0.x;  acc[1] += wB * f0.y;
                    acc[2] += wB * f1.x;  acc[3] += wB * f1.y;
                    acc[4] += wB * f2.x;  acc[5] += wB * f2.y;
                    acc[6] += wB * f3.x;  acc[7] += wB * f3.y;
                }
            }
            if (j < cnt) {
                const int   o = s_off[wrp][j];
                const float w = s_w[wrp][head][j];
                float4 v = __ldg(reinterpret_cast<const float4*>(feath + o) + lane);
                const __half2* hv = reinterpret_cast<const __half2*>(&v);
                float2 f0 = __half22float2(hv[0]), f1 = __half22float2(hv[1]);
                float2 f2 = __half22float2(hv[2]), f3 = __half22float2(hv[3]);
                acc[0] += w * f0.x;  acc[1] += w * f0.y;
                acc[2] += w * f1.x;  acc[3] += w * f1.y;
                acc[4] += w * f2.x;  acc[5] += w * f2.y;
                acc[6] += w * f3.x;  acc[7] += w * f3.y;
            }
        }
        __syncwarp();
    }
    s0 = wred_sum(s0); s1 = wred_sum(s1); s2 = wred_sum(s2);
    const float i0 = s0 > 0.f ? 1.f / s0 : 0.f;
    const float i1 = s1 > 0.f ? 1.f / s1 : 0.f;
    const float i2 = s2 > 0.f ? 1.f / s2 : 0.f;
    const float inv = (head == 0) ? i0 : (head == 1) ? i1 : i2;
#pragma unroll
    for (int k = 0; k < 8; k++) acc[k] *= inv;

#pragma unroll
    for (int k = 0; k < 8; k++) {
        float v8  = __shfl_down_sync(~0u, acc[k], 8);
        float v16 = __shfl_down_sync(~0u, acc[k], 16);
        acc[k] += v8 + v16;
    }
    if (lane < 8) {
        const int c = 8 * lane;
#pragma unroll
        for (int k = 0; k < 8; k++)
            acc[k] += __ldg(&bias[c + k]) + __ldg(&bias[HF + c + k]) + __ldg(&bias[2*HF + c + k]);
        float4 o0 = make_float4(acc[0], acc[1], acc[2], acc[3]);
        float4 o1 = make_float4(acc[4], acc[5], acc[6], acc[7]);
        *reinterpret_cast<float4*>(out + d * HF + c)     = o0;
        *reinterpret_cast<float4*>(out + d * HF + c + 4) = o1;
    }
}

// ================= fused softmax + aggregation, Fo = 2 (layer 3) ============
__global__ void agg_small(const float* __restrict__ feat,
                          const float* __restrict__ bias,
                          float* __restrict__ out) {
    const int lane = threadIdx.x & 31;
    const int d = blockIdx.x * WPB + (threadIdx.x >> 5);
    if (d >= N_NODES) return;
    const int beg = g_rowp[d], end = g_rowp[d + 1];
    const float4 er = *reinterpret_cast<const float4*>(g_er + 4 * d);

    float s0 = 0.f, s1 = 0.f, s2 = 0.f;
    float c00 = 0.f, c01 = 0.f, c10 = 0.f, c11 = 0.f, c20 = 0.f, c21 = 0.f;
    for (int i = beg + lane; i < end; i += 32) {
        int s = __ldg(&g_csrs[i]);
        float4 e = *reinterpret_cast<const float4*>(g_el + 4 * s);
        float w0 = __expf(lrelu(e.x + er.x));
        float w1 = __expf(lrelu(e.y + er.y));
        float w2 = __expf(lrelu(e.z + er.z));
        s0 += w0; s1 += w1; s2 += w2;
        const float* fp = feat + s * HFO3;
        c00 += w0 * __ldg(fp + 0); c01 += w0 * __ldg(fp + 1);
        c10 += w1 * __ldg(fp + 2); c11 += w1 * __ldg(fp + 3);
        c20 += w2 * __ldg(fp + 4); c21 += w2 * __ldg(fp + 5);
    }
    s0 = wred_sum(s0); s1 = wred_sum(s1); s2 = wred_sum(s2);
    c00 = wred_sum(c00); c01 = wred_sum(c01);
    c10 = wred_sum(c10); c11 = wred_sum(c11);
    c20 = wred_sum(c20); c21 = wred_sum(c21);
    if (lane == 0) {
        const float i0 = s0 > 0.f ? 1.f / s0 : 0.f;
        const float i1 = s1 > 0.f ? 1.f / s1 : 0.f;
        const float i2 = s2 > 0.f ? 1.f / s2 : 0.f;
        float b0 = __ldg(&bias[0]) + __ldg(&bias[2]) + __ldg(&bias[4]);
        float b1 = __ldg(&bias[1]) + __ldg(&bias[3]) + __ldg(&bias[5]);
        out[d * NCLS + 0] = c00 * i0 + c10 * i1 + c20 * i2 + b0;
        out[d * NCLS + 1] = c01 * i0 + c11 * i1 + c21 * i2 + b1;
    }
}

// ================= host driver ==============================================
static inline int cdiv(int a, int b) { return (a + b - 1) / b; }

extern "C" void kernel_launch(void* const* d_in, const int* in_sizes, int n_in,
                              void* d_out, int out_size) {
    const float* feats = (const float*)d_in[0];
    const int*   src   = (const int*)  d_in[1];
    const int*   dst   = (const int*)  d_in[2];
    const float* W1 = (const float*)d_in[3],  *al1 = (const float*)d_in[4];
    const float* ar1= (const float*)d_in[5],  *b1  = (const float*)d_in[6];
    const float* W2 = (const float*)d_in[7],  *al2 = (const float*)d_in[8];
    const float* ar2= (const float*)d_in[9],  *b2  = (const float*)d_in[10];
    const float* W3 = (const float*)d_in[11], *al3 = (const float*)d_in[12];
    const float* ar3= (const float*)d_in[13], *b3  = (const float*)d_in[14];
    float* out = (float*)d_out;

    __half2* feath;
    float *h, *feat3;
    int* cnt;
    cudaGetSymbolAddress((void**)&feath, g_feath);
    cudaGetSymbolAddress((void**)&h,     g_h);
    cudaGetSymbolAddress((void**)&feat3, g_feat3);
    cudaGetSymbolAddress((void**)&cnt,   g_cnt);

    const int gE4  = cdiv(N_EDGES / 4, 256);
    const int gDst = cdiv(N_NODES, WPB);

    // -------- CSR build, with layer-1 GEMM fused into the scatter launch ----
    cudaMemsetAsync(cnt, 0, N_NODES * sizeof(int));
    hist_dst<<<gE4, 256>>>((const int4*)dst);
    scan_local<<<SCAN_NB, SCAN_B>>>();
    scan_add2<<<SCAN_NB, SCAN_B>>>();
    gemm1_scatter<<<GT1 + SCB, 192>>>(feats, W1, al1, ar1, feath,
                                      (const int4*)src, (const int4*)dst);

    // -------- layer 1 aggregation --------
    agg_big<<<gDst, 32 * WPB>>>(feath, b1, h);

    // -------- layer 2 (Fin=64, Fo=64) --------
    gemm_attn64<<<GT1, 192>>>(h, W2, al2, ar2, feath);
    agg_big<<<gDst, 32 * WPB>>>(feath, b2, h);

    // -------- layer 3 (Fin=64, Fo=2) --------
    gemm3_attn<<<cdiv(N_NODES, 128), 128>>>(h, W3, al3, ar3);
    agg_small<<<gDst, 32 * WPB>>>(feat3, b3, out);
}